// round 6
// baseline (speedup 1.0000x reference)
#include <cuda_runtime.h>
#include <cuda_fp16.h>
#include <math.h>

// ---------------- problem constants ----------------
#define MAX_NODES 50000
#define MAX_EDGES 800000

// fp16-compressed per-node records: per lane 12 halves = uint4 (8 halves) + uint2 (4 halves)
__device__ uint4 g_node4[MAX_NODES * 32];
__device__ uint2 g_node2[MAX_NODES * 32];

// CSR-by-src scratch
__device__ int g_cnt[MAX_NODES];
__device__ int g_off[MAX_NODES + 1];
__device__ int g_pos[MAX_NODES];
__device__ int g_perm[MAX_EDGES];

// ---- constants derived from the reference's (non-standard) CG formula ----
#define ALPHA0 0.125f
#define ALPHA1 0.10206207261596575f
#define D0 0.6666666666666666f
#define D1 0.3333333333333333f
#define E0 0.6963106238227914f
#define E1 0.17407765595569785f
#define N1 0.48888007f
#define N2 0.04704256f
#define N3 0.06111001f
#define N4 0.12222002f

static __device__ __forceinline__ unsigned pack2(float a, float b) {
    half2 h = __floats2half2_rn(a, b);
    return *reinterpret_cast<unsigned*>(&h);
}
static __device__ __forceinline__ float2 unpack2(unsigned u) {
    half2 h = *reinterpret_cast<half2*>(&u);
    return __half22float2(h);
}

// ---------------- sort kernels: counting sort of edges by src ----------------
__global__ void hist_kernel(const int* __restrict__ eidx, int n_edges) {
    int e = blockIdx.x * blockDim.x + threadIdx.x;
    if (e < n_edges) atomicAdd(&g_cnt[eidx[e]], 1);
}

__global__ void scan_kernel(int n_nodes) {   // single block, 1024 threads
    __shared__ int ssum[1024];
    int t = threadIdx.x;
    const int SEG = (MAX_NODES + 1023) / 1024;   // 49
    int base = t * SEG;
    int s = 0;
    for (int i = 0; i < SEG; i++) {
        int idx = base + i;
        if (idx < n_nodes) s += g_cnt[idx];
    }
    ssum[t] = s;
    __syncthreads();
    for (int d = 1; d < 1024; d <<= 1) {
        int v = (t >= d) ? ssum[t - d] : 0;
        __syncthreads();
        ssum[t] += v;
        __syncthreads();
    }
    int run = (t == 0) ? 0 : ssum[t - 1];
    for (int i = 0; i < SEG; i++) {
        int idx = base + i;
        if (idx < n_nodes) {
            g_off[idx] = run;
            g_pos[idx] = run;
            run += g_cnt[idx];
        }
    }
    if (t == 1023) g_off[n_nodes] = ssum[1023];
}

__global__ void scatter_kernel(const int* __restrict__ eidx, int n_edges) {
    int e = blockIdx.x * blockDim.x + threadIdx.x;
    if (e < n_edges) {
        int p = atomicAdd(&g_pos[eidx[e]], 1);
        g_perm[p] = e;
    }
}

// ---------------- per-node precompute: fold weights + path factors, store fp16 ----------------
__global__ void precompute_kernel(const float* __restrict__ feat,
                                  const float* __restrict__ W,
                                  int n_nodes) {
    __shared__ float Ws[5 * 1024];
    for (int i = threadIdx.x; i < 5 * 1024; i += blockDim.x) {
        int p = i >> 10;
        float s = (p == 0) ? ALPHA0 : (p == 3) ? ALPHA0 : ALPHA1;
        Ws[i] = s * W[i];
    }
    __syncthreads();

    int lane  = threadIdx.x & 31;
    int warp  = (blockIdx.x * blockDim.x + threadIdx.x) >> 5;
    int nwarp = (gridDim.x * blockDim.x) >> 5;

    for (int n = warp; n < n_nodes; n += nwarp) {
        const float* x = feat + (size_t)n * 128;
        float x0  = x[lane];
        float x10 = x[32 + 3 * lane];
        float x11 = x[33 + 3 * lane];
        float x12 = x[34 + 3 * lane];
        float a1 = 0.f, a2 = 0.f;
        float b3[3] = {0.f, 0.f, 0.f}, b4[3] = {0.f, 0.f, 0.f}, b5[3] = {0.f, 0.f, 0.f};
        #pragma unroll
        for (int u = 0; u < 32; u++) {
            float xu = __shfl_sync(0xFFFFFFFFu, x0,  u);
            float y0 = __shfl_sync(0xFFFFFFFFu, x10, u);
            float y1 = __shfl_sync(0xFFFFFFFFu, x11, u);
            float y2 = __shfl_sync(0xFFFFFFFFu, x12, u);
            float w0 = Ws[          u * 32 + lane];
            float w1 = Ws[1024 +    u * 32 + lane];
            float w2 = Ws[2048 +    u * 32 + lane];
            float w3 = Ws[3072 +    u * 32 + lane];
            float w4 = Ws[4096 +    u * 32 + lane];
            a1 = fmaf(xu, w0, a1);
            a2 = fmaf(xu, w1, a2);
            b3[0] = fmaf(y0, w2, b3[0]); b3[1] = fmaf(y1, w2, b3[1]); b3[2] = fmaf(y2, w2, b3[2]);
            b4[0] = fmaf(y0, w3, b4[0]); b4[1] = fmaf(y1, w3, b4[1]); b4[2] = fmaf(y2, w3, b4[2]);
            b5[0] = fmaf(y0, w4, b5[0]); b5[1] = fmaf(y1, w4, b5[1]); b5[2] = fmaf(y2, w4, b5[2]);
        }
        b3[0] *= D0; b3[1] *= D1; b3[2] *= D0;   // path (1,0,1): diag(2,1,2)/3
        b4[0] *= E0; b4[1] *= E1; b4[2] *= E0;   // path (1,1,0): diag(4,1,4)/sqrt(33)

        uint4 p;
        p.x = pack2(a1,   a2);
        p.y = pack2(b3[0], b3[1]);
        p.z = pack2(b3[2], b4[0]);
        p.w = pack2(b4[1], b4[2]);
        uint2 q;
        q.x = pack2(b5[0], b5[1]);
        q.y = pack2(b5[2], 0.f);
        g_node4[n * 32 + lane] = p;
        g_node2[n * 32 + lane] = q;
    }
}

// ---------------- per-src-node CSR edge kernel: record in registers, loop run ----------------
__global__ void __launch_bounds__(256) edge_csr_kernel(const float* __restrict__ sh,
                                                       const int* __restrict__ eidx,
                                                       float* __restrict__ out,
                                                       int n_edges, int n_nodes) {
    const unsigned FULL = 0xFFFFFFFFu;
    int lane = threadIdx.x & 31;
    int node = (blockIdx.x * blockDim.x + threadIdx.x) >> 5;
    if (node >= n_nodes) return;
    int beg = g_off[node], end = g_off[node + 1];
    if (beg >= end) return;

    // gather record once (registers, reused for whole run)
    uint4 rp = g_node4[node * 32 + lane];
    uint2 rq = g_node2[node * 32 + lane];
    float2 u0 = unpack2(rp.x);
    float2 u1 = unpack2(rp.y);
    float2 u2 = unpack2(rp.z);
    float2 u3 = unpack2(rp.w);
    float2 u4 = unpack2(rq.x);
    float2 u5 = unpack2(rq.y);
    float a1 = u0.x, a2 = u0.y;
    float b3x = u1.x, b3y = u1.y, b3z = u2.x;
    float b4x = u2.y, b4y = u3.x, b4z = u3.y;
    float b5x = u4.x, b5y = u4.y, b5z = u5.x;

    // loop-invariant shuffle-transpose control (lane-constant)
    int tp[4], tsl[4], tk[4];
    #pragma unroll
    for (int j = 0; j < 4; j++) {
        int p = 4 * lane + j;
        int q = p - 32;
        int w = (q >= 0) ? (q / 3) : 0;
        tk[j]  = q - 3 * w;
        tsl[j] = (p < 32) ? p : w;
        tp[j]  = (p < 32);
    }

    for (int base = beg; base < end; base += 32) {
        int m = min(32, end - base);
        int idx = base + ((lane < m) ? lane : 0);
        int e_l   = g_perm[idx];                   // coalesced
        int dst_l = eidx[n_edges + e_l];           // one gather instr for whole chunk

        int e0 = __shfl_sync(FULL, e_l, 0);
        float sv = (lane < 9) ? sh[(size_t)e0 * 9 + lane] : 0.f;

        for (int j = 0; j < m; j++) {
            // prefetch next edge's sh while computing this one
            float svn = 0.f;
            if (j + 1 < m) {
                int e1 = __shfl_sync(FULL, e_l, j + 1);
                svn = (lane < 9) ? sh[(size_t)e1 * 9 + lane] : 0.f;
            }
            int dst = __shfl_sync(FULL, dst_l, j);

            float s0  = __shfl_sync(FULL, sv, 0);
            float s1x = __shfl_sync(FULL, sv, 1);
            float s1y = __shfl_sync(FULL, sv, 2);
            float s1z = __shfl_sync(FULL, sv, 3);
            float q0  = __shfl_sync(FULL, sv, 4);
            float q1v = __shfl_sync(FULL, sv, 5);
            float q2  = __shfl_sync(FULL, sv, 6);
            float q3  = __shfl_sync(FULL, sv, 7);
            float q4  = __shfl_sync(FULL, sv, 8);

            float n2q2 = N2 * q2;
            float n1q4 = N1 * q4;
            float n1q0 = N1 * q0;
            float n3q1 = N3 * q1v;
            float n4q1 = N4 * q1v;
            float n3q3 = N3 * q3;
            float n4q3 = N4 * q3;

            // out0: paths (0,0,0) and (1,1,0)
            float m0 = s0 * a1;
            m0 = fmaf(s1x, b4x, m0);
            m0 = fmaf(s1y, b4y, m0);
            m0 = fmaf(s1z, b4z, m0);

            // out1: paths (0,1,1), (1,0,1), (1,2,1)
            float m1x = fmaf(D0 * s1x, a2,
                        fmaf(s0, b3x,
                        fmaf(-(n2q2 + n1q4), b5x,
                        fmaf(n3q1, b5y, n1q0 * b5z))));
            float m1y = fmaf(D1 * s1y, a2,
                        fmaf(s0, b3y,
                        fmaf(n4q1, b5x,
                        fmaf(n2q2, b5y, n4q3 * b5z))));
            float m1z = fmaf(D0 * s1z, a2,
                        fmaf(s0, b3z,
                        fmaf(n1q0, b5x,
                        fmaf(n3q3, b5y, (n1q4 - n2q2) * b5z))));

            // shuffle-transpose: lane l gathers out positions 4l..4l+3
            float v[4];
            #pragma unroll
            for (int jj = 0; jj < 4; jj++) {
                float t0 = __shfl_sync(FULL, m0,  tsl[jj]);
                float t1 = __shfl_sync(FULL, m1x, tsl[jj]);
                float t2 = __shfl_sync(FULL, m1y, tsl[jj]);
                float t3 = __shfl_sync(FULL, m1z, tsl[jj]);
                v[jj] = tp[jj] ? t0 : ((tk[jj] == 0) ? t1 : (tk[jj] == 1) ? t2 : t3);
            }

            float* dptr = out + (size_t)dst * 128 + 4 * lane;
            asm volatile("red.global.add.v4.f32 [%0], {%1,%2,%3,%4};"
                         :: "l"(dptr), "f"(v[0]), "f"(v[1]), "f"(v[2]), "f"(v[3]) : "memory");

            sv = svn;
        }
    }
}

// ---------------- launch ----------------
extern "C" void kernel_launch(void* const* d_in, const int* in_sizes, int n_in,
                              void* d_out, int out_size) {
    const float* feat = (const float*)d_in[0];
    const float* sh   = (const float*)d_in[1];
    const int*   eidx = (const int*)d_in[2];
    const float* W    = (const float*)d_in[3];
    int n_nodes = in_sizes[0] / 128;
    int n_edges = in_sizes[2] / 2;

    void* cnt_ptr = nullptr;
    cudaGetSymbolAddress(&cnt_ptr, g_cnt);

    cudaMemsetAsync(d_out, 0, (size_t)out_size * sizeof(float));
    cudaMemsetAsync(cnt_ptr, 0, (size_t)n_nodes * sizeof(int));

    int eb = (n_edges + 255) / 256;
    hist_kernel<<<eb, 256>>>(eidx, n_edges);
    scan_kernel<<<1, 1024>>>(n_nodes);
    scatter_kernel<<<eb, 256>>>(eidx, n_edges);
    precompute_kernel<<<(n_nodes + 7) / 8, 256>>>(feat, W, n_nodes);

    int nb = (n_nodes * 32 + 255) / 256;
    edge_csr_kernel<<<nb, 256>>>(sh, eidx, (float*)d_out, n_edges, n_nodes);
}

// round 7
// speedup vs baseline: 1.3365x; 1.3365x over previous
#include <cuda_runtime.h>
#include <cuda_fp16.h>
#include <math.h>

// ---------------- problem constants ----------------
#define MAX_NODES 50000

// fp16-compressed per-node records: per lane 12 halves = uint4 (8 halves) + uint2 (4 halves)
__device__ uint4 g_node4[MAX_NODES * 32];
__device__ uint2 g_node2[MAX_NODES * 32];

// ---- constants derived from the reference's (non-standard) CG formula ----
#define ALPHA0 0.125f
#define ALPHA1 0.10206207261596575f
#define D0 0.6666666666666666f
#define D1 0.3333333333333333f
#define E0 0.6963106238227914f
#define E1 0.17407765595569785f
#define N1 0.48888007f
#define N2 0.04704256f
#define N3 0.06111001f
#define N4 0.12222002f

#define NPW 4   // nodes per warp in precompute

static __device__ __forceinline__ unsigned pack2(float a, float b) {
    half2 h = __floats2half2_rn(a, b);
    return *reinterpret_cast<unsigned*>(&h);
}
static __device__ __forceinline__ float2 unpack2(unsigned u) {
    half2 h = *reinterpret_cast<half2*>(&u);
    return __half22float2(h);
}

// ---------------- per-node precompute: 4 nodes/warp, lane = output channel ----------------
__global__ void __launch_bounds__(256) precompute_kernel(const float* __restrict__ feat,
                                                         const float* __restrict__ W,
                                                         int n_nodes) {
    __shared__ float Ws[5 * 1024];
    __shared__ float4 xs[8][NPW * 32];   // per-warp staging: [warp][nn*32+u] = (x0,y0,y1,y2)

    for (int i = threadIdx.x; i < 5 * 1024; i += blockDim.x) {
        int p = i >> 10;
        float s = (p == 0 || p == 3) ? ALPHA0 : ALPHA1;
        Ws[i] = s * W[i];
    }
    __syncthreads();

    int lane = threadIdx.x & 31;
    int wl   = threadIdx.x >> 5;
    int warp = (blockIdx.x * blockDim.x + threadIdx.x) >> 5;
    int nwarp = (gridDim.x * blockDim.x) >> 5;

    for (int nb = warp * NPW; nb < n_nodes; nb += nwarp * NPW) {
        // stage 4 nodes' inputs: float4(x0[u], y0[u], y1[u], y2[u]), u = lane
        #pragma unroll
        for (int nn = 0; nn < NPW; nn++) {
            int n = nb + nn;
            float4 v = make_float4(0.f, 0.f, 0.f, 0.f);
            if (n < n_nodes) {
                const float* x = feat + (size_t)n * 128;
                v.x = x[lane];
                v.y = x[32 + 3 * lane];
                v.z = x[33 + 3 * lane];
                v.w = x[34 + 3 * lane];
            }
            xs[wl][nn * 32 + lane] = v;
        }
        __syncwarp();

        float a1[NPW], a2[NPW], b3[NPW][3], b4[NPW][3], b5[NPW][3];
        #pragma unroll
        for (int nn = 0; nn < NPW; nn++) {
            a1[nn] = 0.f; a2[nn] = 0.f;
            #pragma unroll
            for (int k = 0; k < 3; k++) { b3[nn][k] = 0.f; b4[nn][k] = 0.f; b5[nn][k] = 0.f; }
        }

        #pragma unroll 4
        for (int u = 0; u < 32; u++) {
            float w0 = Ws[          u * 32 + lane];
            float w1 = Ws[1024 +    u * 32 + lane];
            float w2 = Ws[2048 +    u * 32 + lane];
            float w3 = Ws[3072 +    u * 32 + lane];
            float w4 = Ws[4096 +    u * 32 + lane];
            #pragma unroll
            for (int nn = 0; nn < NPW; nn++) {
                float4 v = xs[wl][nn * 32 + u];   // broadcast (all lanes same addr)
                a1[nn] = fmaf(v.x, w0, a1[nn]);
                a2[nn] = fmaf(v.x, w1, a2[nn]);
                b3[nn][0] = fmaf(v.y, w2, b3[nn][0]);
                b3[nn][1] = fmaf(v.z, w2, b3[nn][1]);
                b3[nn][2] = fmaf(v.w, w2, b3[nn][2]);
                b4[nn][0] = fmaf(v.y, w3, b4[nn][0]);
                b4[nn][1] = fmaf(v.z, w3, b4[nn][1]);
                b4[nn][2] = fmaf(v.w, w3, b4[nn][2]);
                b5[nn][0] = fmaf(v.y, w4, b5[nn][0]);
                b5[nn][1] = fmaf(v.z, w4, b5[nn][1]);
                b5[nn][2] = fmaf(v.w, w4, b5[nn][2]);
            }
        }

        #pragma unroll
        for (int nn = 0; nn < NPW; nn++) {
            int n = nb + nn;
            if (n >= n_nodes) break;
            float c30 = b3[nn][0] * D0, c31 = b3[nn][1] * D1, c32 = b3[nn][2] * D0;
            float c40 = b4[nn][0] * E0, c41 = b4[nn][1] * E1, c42 = b4[nn][2] * E0;
            uint4 p;
            p.x = pack2(a1[nn], a2[nn]);
            p.y = pack2(c30, c31);
            p.z = pack2(c32, c40);
            p.w = pack2(c41, c42);
            uint2 q;
            q.x = pack2(b5[nn][0], b5[nn][1]);
            q.y = pack2(b5[nn][2], 0.f);
            g_node4[n * 32 + lane] = p;
            g_node2[n * 32 + lane] = q;
        }
        __syncwarp();
    }
}

// ---------------- per-edge: gather fp16 record (prefetched), combine with sh, red.v4 ----------------
__global__ void __launch_bounds__(256) edge_kernel(const float* __restrict__ sh,
                                                   const int* __restrict__ eidx,
                                                   float* __restrict__ out,
                                                   int n_edges) {
    const unsigned FULL = 0xFFFFFFFFu;
    int lane  = threadIdx.x & 31;
    int warp  = (blockIdx.x * blockDim.x + threadIdx.x) >> 5;
    int nwarp = (gridDim.x * blockDim.x) >> 5;

    // loop-invariant shuffle-transpose control (lane-constant)
    int tp[4], tsl[4], tk[4];
    #pragma unroll
    for (int j = 0; j < 4; j++) {
        int p = 4 * lane + j;
        int q = p - 32;
        int w = (q >= 0) ? (q / 3) : 0;
        tk[j]  = q - 3 * w;
        tsl[j] = (p < 32) ? p : w;
        tp[j]  = (p < 32);
    }

    int e = warp;
    int dst = 0;
    float sv = 0.f;
    uint4 rp = make_uint4(0, 0, 0, 0);
    uint2 rq = make_uint2(0, 0);
    if (e < n_edges) {
        int src = eidx[e];
        dst = eidx[n_edges + e];
        sv  = (lane < 9) ? sh[(size_t)e * 9 + lane] : 0.f;
        rp  = g_node4[src * 32 + lane];
        rq  = g_node2[src * 32 + lane];
    }

    while (e < n_edges) {
        // prefetch everything for the next edge first (deepest latency chains)
        int en = e + nwarp;
        int ndst = 0;
        float nsv = 0.f;
        uint4 nrp = make_uint4(0, 0, 0, 0);
        uint2 nrq = make_uint2(0, 0);
        if (en < n_edges) {
            int nsrc = eidx[en];
            ndst = eidx[n_edges + en];
            nsv  = (lane < 9) ? sh[(size_t)en * 9 + lane] : 0.f;
            nrp  = g_node4[nsrc * 32 + lane];
            nrq  = g_node2[nsrc * 32 + lane];
        }

        // broadcast sh components
        float s0  = __shfl_sync(FULL, sv, 0);
        float s1x = __shfl_sync(FULL, sv, 1);
        float s1y = __shfl_sync(FULL, sv, 2);
        float s1z = __shfl_sync(FULL, sv, 3);
        float q0  = __shfl_sync(FULL, sv, 4);
        float q1v = __shfl_sync(FULL, sv, 5);
        float q2  = __shfl_sync(FULL, sv, 6);
        float q3  = __shfl_sync(FULL, sv, 7);
        float q4  = __shfl_sync(FULL, sv, 8);

        float n2q2 = N2 * q2;
        float n1q4 = N1 * q4;
        float n1q0 = N1 * q0;
        float n3q1 = N3 * q1v;
        float n4q1 = N4 * q1v;
        float n3q3 = N3 * q3;
        float n4q3 = N4 * q3;

        float2 u0 = unpack2(rp.x);   // a1, a2
        float2 u1 = unpack2(rp.y);   // b3x, b3y
        float2 u2 = unpack2(rp.z);   // b3z, b4x
        float2 u3 = unpack2(rp.w);   // b4y, b4z
        float2 u4 = unpack2(rq.x);   // b5x, b5y
        float2 u5 = unpack2(rq.y);   // b5z, -
        float a1 = u0.x, a2 = u0.y;
        float b3x = u1.x, b3y = u1.y, b3z = u2.x;
        float b4x = u2.y, b4y = u3.x, b4z = u3.y;
        float b5x = u4.x, b5y = u4.y, b5z = u5.x;

        // out0: paths (0,0,0) and (1,1,0)
        float m0 = s0 * a1;
        m0 = fmaf(s1x, b4x, m0);
        m0 = fmaf(s1y, b4y, m0);
        m0 = fmaf(s1z, b4z, m0);

        // out1: paths (0,1,1), (1,0,1), (1,2,1)
        float m1x = fmaf(D0 * s1x, a2,
                    fmaf(s0, b3x,
                    fmaf(-(n2q2 + n1q4), b5x,
                    fmaf(n3q1, b5y, n1q0 * b5z))));
        float m1y = fmaf(D1 * s1y, a2,
                    fmaf(s0, b3y,
                    fmaf(n4q1, b5x,
                    fmaf(n2q2, b5y, n4q3 * b5z))));
        float m1z = fmaf(D0 * s1z, a2,
                    fmaf(s0, b3z,
                    fmaf(n1q0, b5x,
                    fmaf(n3q3, b5y, (n1q4 - n2q2) * b5z))));

        // shuffle-transpose: lane l gathers out positions 4l..4l+3
        float v[4];
        #pragma unroll
        for (int j = 0; j < 4; j++) {
            float t0 = __shfl_sync(FULL, m0,  tsl[j]);
            float t1 = __shfl_sync(FULL, m1x, tsl[j]);
            float t2 = __shfl_sync(FULL, m1y, tsl[j]);
            float t3 = __shfl_sync(FULL, m1z, tsl[j]);
            v[j] = tp[j] ? t0 : ((tk[j] == 0) ? t1 : (tk[j] == 1) ? t2 : t3);
        }

        float* dptr = out + (size_t)dst * 128 + 4 * lane;
        asm volatile("red.global.add.v4.f32 [%0], {%1,%2,%3,%4};"
                     :: "l"(dptr), "f"(v[0]), "f"(v[1]), "f"(v[2]), "f"(v[3]) : "memory");

        e = en; dst = ndst; sv = nsv; rp = nrp; rq = nrq;
    }
}

// ---------------- launch ----------------
extern "C" void kernel_launch(void* const* d_in, const int* in_sizes, int n_in,
                              void* d_out, int out_size) {
    const float* feat = (const float*)d_in[0];
    const float* sh   = (const float*)d_in[1];
    const int*   eidx = (const int*)d_in[2];
    const float* W    = (const float*)d_in[3];
    int n_nodes = in_sizes[0] / 128;
    int n_edges = in_sizes[2] / 2;

    cudaMemsetAsync(d_out, 0, (size_t)out_size * sizeof(float));

    int warps_needed = (n_nodes + NPW - 1) / NPW;
    int pre_blocks = (warps_needed + 7) / 8;
    precompute_kernel<<<pre_blocks, 256>>>(feat, W, n_nodes);
    edge_kernel<<<2048, 256>>>(sh, eidx, (float*)d_out, n_edges);
}